// round 16
// baseline (speedup 1.0000x reference)
#include <cuda_runtime.h>
#include <cuda_fp16.h>
#include <cstdint>

#define N_NODES 50000
#define N_EDGES 800000
#define FEAT    128
#define NUM_RELS 8
#define NSLOT   (NUM_RELS + 1)
#define M_TILES ((N_NODES + 127) / 128)   // 391
#define PCTA    16                        // persistent CTAs per relation
#define GTHREADS 512                      // GEMM block size (16 warps)

#define SCAN_BLK 512
#define NB_SCAN  ((N_NODES + SCAN_BLK - 1) / SCAN_BLK)   // 98

// ---------------- scratch (__device__ globals; allocation-free rule) -------
__device__ __half d_msg[(size_t)NUM_RELS * N_NODES * FEAT];  // 102.4 MB fp16 messages (+bias)
__device__ __half d_self[(size_t)N_NODES * FEAT];            // 12.8 MB fp16 self transform (+bias)
__device__ __half d_hf[(size_t)N_NODES * FEAT];              // 12.8 MB fp16 copy of h
__device__ __half d_wt[(size_t)NSLOT * FEAT * FEAT];         // W^T fp16 [r][out][in]
__device__ int d_cnt[N_NODES];
__device__ int d_off[N_NODES];
__device__ int d_cur[N_NODES];
__device__ int d_bsum[NB_SCAN];
__device__ int d_rows[N_EDGES];                              // rel*N_NODES+src, binned by dst

// ---------------- cp.async helpers ----------------------------------------
#define CP_ASYNC16(saddr, gptr) \
    asm volatile("cp.async.cg.shared.global [%0], [%1], 16;" \
                 :: "r"(saddr), "l"(gptr) : "memory")
#define CP_COMMIT() asm volatile("cp.async.commit_group;" ::: "memory")
#define CP_WAIT0()  asm volatile("cp.async.wait_group 0;" ::: "memory")

__device__ __forceinline__ uint32_t smem_to_u32(const void* p) {
    uint32_t a;
    asm("{ .reg .u64 t; cvta.to.shared.u64 t, %1; cvt.u32.u64 %0, t; }"
        : "=r"(a) : "l"(p));
    return a;
}

// ---------------------------------------------------------------------------
// Prepass (fused): h fp32->fp16 copy  +  W transpose fp32->fp16
// ---------------------------------------------------------------------------
#define H_CHUNKS (N_NODES * FEAT / 4)     // 1.6M float4 chunks
__global__ void prep_kernel(const float* __restrict__ h, const float* __restrict__ w) {
    int idx = blockIdx.x * blockDim.x + threadIdx.x;
    if (idx < H_CHUNKS) {
        float4 v = __ldg((const float4*)h + idx);
        __half2 a = __floats2half2_rn(v.x, v.y);
        __half2 b = __floats2half2_rn(v.z, v.w);
        *((uint2*)d_hf + idx) = make_uint2(*(uint32_t*)&a, *(uint32_t*)&b);
    }
    if (idx < NSLOT * FEAT * FEAT) {
        int r   = idx / (FEAT * FEAT);
        int rem = idx - r * (FEAT * FEAT);
        int n   = rem >> 7;          // out dim
        int k   = rem & 127;         // in dim
        d_wt[idx] = __float2half_rn(
            __ldg(w + (size_t)r * FEAT * FEAT + (size_t)k * FEAT + n));
    }
}

// ---------------------------------------------------------------------------
// Phase 1: hwb[r] = h @ W[r] + b[r]; persistent CTAs, double-buffered fp16 A,
// single-pass fp16 MMA. 512 threads, 4m x 4n warps, 32x32 warp tile.
// ---------------------------------------------------------------------------
#define LDK 136                           // padded row stride in fp16 elems
#define TILE_BYTES (128 * LDK * 2)        // 34816
#define SM_A0 0
#define SM_A1 TILE_BYTES
#define SM_B  (2 * TILE_BYTES)
#define SMEM_BYTES (3 * TILE_BYTES)       // 104448

__device__ __forceinline__ void mma16816(float* c, const uint32_t* a, const uint32_t* b) {
    asm volatile(
        "mma.sync.aligned.m16n8k16.row.col.f32.f16.f16.f32 "
        "{%0,%1,%2,%3}, {%4,%5,%6,%7}, {%8,%9}, {%0,%1,%2,%3};"
        : "+f"(c[0]), "+f"(c[1]), "+f"(c[2]), "+f"(c[3])
        : "r"(a[0]), "r"(a[1]), "r"(a[2]), "r"(a[3]), "r"(b[0]), "r"(b[1]));
}

// prefetch one 128x128 fp16 A tile: 128 rows x 16 chunks(16B) = 2048 cp.async
__device__ __forceinline__ void prefetch_tile(int m0, uint32_t abuf_u32, int tid) {
#pragma unroll
    for (int it = 0; it < 4; it++) {
        int c   = it * GTHREADS + tid;
        int row = c >> 4;
        int ch  = c & 15;                 // 16B chunk within row
        int m   = m0 + row;
        if (m > N_NODES - 1) m = N_NODES - 1;   // clamp; stores masked later
        CP_ASYNC16(abuf_u32 + (uint32_t)(row * (LDK * 2) + ch * 16),
                   d_hf + (size_t)m * FEAT + ch * 8);
    }
    CP_COMMIT();
}

__global__ void __launch_bounds__(GTHREADS, 1)
gemm_mma_kernel(const float* __restrict__ bias) {
    extern __shared__ char smem[];
    __half* As[2] = { (__half*)(smem + SM_A0), (__half*)(smem + SM_A1) };
    __half* Bs    = (__half*)(smem + SM_B);
    const uint32_t a_u32[2] = { smem_to_u32(As[0]), smem_to_u32(As[1]) };

    const int r    = blockIdx.x;
    const int y0   = blockIdx.y;
    const int tid  = threadIdx.x;
    const int wid  = tid >> 5;
    const int lane = tid & 31;
    const int g    = lane >> 2;          // group id 0..7
    const int t    = lane & 3;           // thread-in-group 0..3

    // warp tiling: 4 (m) x 4 (n); warp tile 32x32
    const int wm = (wid >> 2) * 32;
    const int wn = (wid & 3) * 32;

    // ---- prefetch first A tile into buffer 0 ----
    prefetch_tile(y0 * 128, a_u32[0], tid);

    // ---- B: W^T fp16 rows [n][k] — loaded ONCE per CTA ----
    const __half* bw = d_wt + (size_t)r * FEAT * FEAT;
#pragma unroll
    for (int it = 0; it < 4; it++) {
        int c    = it * GTHREADS + tid;
        int row  = c >> 4;
        int col8 = (c & 15) << 3;
        *(uint4*)(Bs + row * LDK + col8) = *(const uint4*)(bw + (size_t)row * FEAT + col8);
    }

    // unified fp16 output target: message slot r, or the self slot
    __half* outr = (r < NUM_RELS) ? (d_msg + (size_t)r * N_NODES * FEAT) : d_self;

    // ---- persistent loop over m-tiles ----
    int cur = 0;
    for (int tile = y0; tile < M_TILES; tile += PCTA) {
        const int m0 = tile * 128;

        CP_WAIT0();
        __syncthreads();   // As[cur] ready; B visible (1st iter); As[cur^1] free

        // prefetch next tile into the other buffer (overlaps mainloop+epilogue)
        const int nxt = tile + PCTA;
        if (nxt < M_TILES) prefetch_tile(nxt * 128, a_u32[cur ^ 1], tid);

        const __half* A = As[cur];

        // ---- mainloop: single fp16 pass ----
        float acc[2][4][4];
#pragma unroll
        for (int i = 0; i < 2; i++)
#pragma unroll
            for (int j = 0; j < 4; j++)
#pragma unroll
                for (int q = 0; q < 4; q++) acc[i][j][q] = 0.0f;

#pragma unroll
        for (int ks = 0; ks < 8; ks++) {
            const int kc = ks * 16 + 2 * t;

            uint32_t af[2][4];
#pragma unroll
            for (int mf = 0; mf < 2; mf++) {
                int r0 = (wm + mf * 16 + g) * LDK;
                int r1 = r0 + 8 * LDK;
                af[mf][0] = *(const uint32_t*)(A + r0 + kc);
                af[mf][1] = *(const uint32_t*)(A + r1 + kc);
                af[mf][2] = *(const uint32_t*)(A + r0 + kc + 8);
                af[mf][3] = *(const uint32_t*)(A + r1 + kc + 8);
            }
            uint32_t bf[4][2];
#pragma unroll
            for (int nf = 0; nf < 4; nf++) {
                int nr = (wn + nf * 8 + g) * LDK;
                bf[nf][0] = *(const uint32_t*)(Bs + nr + kc);
                bf[nf][1] = *(const uint32_t*)(Bs + nr + kc + 8);
            }
#pragma unroll
            for (int mf = 0; mf < 2; mf++)
#pragma unroll
                for (int nf = 0; nf < 4; nf++)
                    mma16816(acc[mf][nf], af[mf], bf[nf]);
        }

        // ---- epilogue: + bias, fp16 store (messages and self alike) ----
#pragma unroll
        for (int nf = 0; nf < 4; nf++) {
            const int n0 = wn + nf * 8 + 2 * t;
            const float2 bv = __ldg((const float2*)(bias + (size_t)r * FEAT + n0));
#pragma unroll
            for (int mf = 0; mf < 2; mf++) {
                int mrow0 = m0 + wm + mf * 16 + g;
                int mrow1 = mrow0 + 8;
                if (mrow0 < N_NODES)
                    *(__half2*)(outr + (size_t)mrow0 * FEAT + n0) =
                        __floats2half2_rn(acc[mf][nf][0] + bv.x, acc[mf][nf][1] + bv.y);
                if (mrow1 < N_NODES)
                    *(__half2*)(outr + (size_t)mrow1 * FEAT + n0) =
                        __floats2half2_rn(acc[mf][nf][2] + bv.x, acc[mf][nf][3] + bv.y);
            }
        }
        cur ^= 1;
    }
}

// ---------------------------------------------------------------------------
// CSR build (side stream): zero -> count -> scanA -> scanB -> scatter
// ---------------------------------------------------------------------------
__global__ void zero_cnt_kernel() {
    int g = blockIdx.x * blockDim.x + threadIdx.x;
    if (g < N_NODES) d_cnt[g] = 0;
}

__global__ void count_kernel(const int* __restrict__ dst) {
    int e = blockIdx.x * blockDim.x + threadIdx.x;
    if (e < N_EDGES) atomicAdd(&d_cnt[__ldg(dst + e)], 1);
}

__global__ void __launch_bounds__(SCAN_BLK)
scanA_kernel() {
    __shared__ int s[SCAN_BLK];
    const int t = threadIdx.x;
    const int g = blockIdx.x * SCAN_BLK + t;
    int v = (g < N_NODES) ? d_cnt[g] : 0;
    s[t] = v;
    __syncthreads();
#pragma unroll
    for (int ofs = 1; ofs < SCAN_BLK; ofs <<= 1) {
        int add = (t >= ofs) ? s[t - ofs] : 0;
        __syncthreads();
        s[t] += add;
        __syncthreads();
    }
    if (g < N_NODES) d_off[g] = s[t] - v;           // local exclusive
    if (t == SCAN_BLK - 1) d_bsum[blockIdx.x] = s[t];
}

__global__ void __launch_bounds__(SCAN_BLK)
scanB_kernel() {
    __shared__ int bs[NB_SCAN];
    const int t = threadIdx.x;
    if (t < NB_SCAN) bs[t] = d_bsum[t];
    __syncthreads();
    int p = 0;
    for (int i = 0; i < blockIdx.x; i++) p += bs[i];
    const int g = blockIdx.x * SCAN_BLK + t;
    if (g < N_NODES) {
        int o = d_off[g] + p;
        d_off[g] = o;
        d_cur[g] = o;
    }
}

__global__ void scatter_kernel(const int* __restrict__ src,
                               const int* __restrict__ dst,
                               const int* __restrict__ rel) {
    int e = blockIdx.x * blockDim.x + threadIdx.x;
    if (e >= N_EDGES) return;
    int d = __ldg(dst + e);
    int pos = atomicAdd(&d_cur[d], 1);
    d_rows[pos] = __ldg(rel + e) * N_NODES + __ldg(src + e);
}

// ---------------------------------------------------------------------------
// Aggregation + finalize: warp per dst node, fp16 max-reduce, fused ReLU
// ---------------------------------------------------------------------------
__global__ void __launch_bounds__(256)
agg_finalize_kernel(float* __restrict__ out) {
    const int gid  = blockIdx.x * blockDim.x + threadIdx.x;
    const int nid  = gid >> 5;
    const int lane = gid & 31;
    if (nid >= N_NODES) return;

    const int deg = d_cnt[nid];
    const int off = d_off[nid];

    __half2 acc0 = __float2half2_rn(-65504.f);
    __half2 acc1 = acc0;

    int i = 0;
    for (; i + 2 <= deg; i += 2) {
        const int r0 = __ldg(&d_rows[off + i]);
        const int r1 = __ldg(&d_rows[off + i + 1]);
        const uint2 v0 = __ldg((const uint2*)(d_msg + (size_t)r0 * FEAT) + lane);
        const uint2 v1 = __ldg((const uint2*)(d_msg + (size_t)r1 * FEAT) + lane);
        acc0 = __hmax2(acc0, __hmax2(*(const __half2*)&v0.x, *(const __half2*)&v1.x));
        acc1 = __hmax2(acc1, __hmax2(*(const __half2*)&v0.y, *(const __half2*)&v1.y));
    }
    if (i < deg) {
        const int r0 = __ldg(&d_rows[off + i]);
        const uint2 v0 = __ldg((const uint2*)(d_msg + (size_t)r0 * FEAT) + lane);
        acc0 = __hmax2(acc0, *(const __half2*)&v0.x);
        acc1 = __hmax2(acc1, *(const __half2*)&v0.y);
    }

    float2 f0 = __half22float2(acc0);
    float2 f1 = __half22float2(acc1);
    if (deg == 0) { f0 = make_float2(0.f, 0.f); f1 = f0; }

    const uint2 sv = __ldg((const uint2*)(d_self + (size_t)nid * FEAT) + lane);
    const float2 s0 = __half22float2(*(const __half2*)&sv.x);
    const float2 s1 = __half22float2(*(const __half2*)&sv.y);

    float4 res;
    res.x = fmaxf(s0.x + f0.x, 0.0f);
    res.y = fmaxf(s0.y + f0.y, 0.0f);
    res.z = fmaxf(s1.x + f1.x, 0.0f);
    res.w = fmaxf(s1.y + f1.y, 0.0f);
    *(float4*)(out + (size_t)nid * FEAT + lane * 4) = res;
}

// ---------------------------------------------------------------------------
extern "C" void kernel_launch(void* const* d_in, const int* in_sizes, int n_in,
                              void* d_out, int out_size) {
    const float* h    = (const float*)d_in[0];
    const float* w    = (const float*)d_in[1];
    const float* bias = (const float*)d_in[2];
    const int*   src  = (const int*)d_in[3];
    const int*   dst  = (const int*)d_in[4];
    const int*   rel  = (const int*)d_in[5];
    float*       out  = (float*)d_out;

    // One-time resource creation (first call happens outside graph capture).
    static cudaStream_t s_side = nullptr;
    static cudaEvent_t  ev_fork = nullptr, ev_join = nullptr;
    if (!s_side) {
        cudaStreamCreateWithFlags(&s_side, cudaStreamNonBlocking);
        cudaEventCreateWithFlags(&ev_fork, cudaEventDisableTiming);
        cudaEventCreateWithFlags(&ev_join, cudaEventDisableTiming);
        cudaFuncSetAttribute(gemm_mma_kernel,
                             cudaFuncAttributeMaxDynamicSharedMemorySize, SMEM_BYTES);
    }

    // Fork: CSR build on side stream, GEMM chain on main stream.
    // Submission order keeps gemm 4th so ncu profiles it.
    cudaEventRecord(ev_fork, 0);
    cudaStreamWaitEvent(s_side, ev_fork, 0);

    zero_cnt_kernel<<<(N_NODES + 255) / 256, 256, 0, s_side>>>();       // 1
    count_kernel<<<(N_EDGES + 255) / 256, 256, 0, s_side>>>(dst);       // 2

    prep_kernel<<<(H_CHUNKS + 255) / 256, 256>>>(h, w);                 // 3 (main)
    gemm_mma_kernel<<<dim3(NSLOT, PCTA), GTHREADS, SMEM_BYTES>>>(bias); // 4 (main)

    scanA_kernel<<<NB_SCAN, SCAN_BLK, 0, s_side>>>();                   // 5
    scanB_kernel<<<NB_SCAN, SCAN_BLK, 0, s_side>>>();                   // 6
    scatter_kernel<<<(N_EDGES + 255) / 256, 256, 0, s_side>>>(src, dst, rel); // 7

    // Join, then aggregate+finalize (depends on both branches).
    cudaEventRecord(ev_join, s_side);
    cudaStreamWaitEvent(0, ev_join, 0);

    const long long agg_threads = (long long)N_NODES * 32;
    agg_finalize_kernel<<<(int)((agg_threads + 255) / 256), 256>>>(out);
}

// round 17
// speedup vs baseline: 1.0363x; 1.0363x over previous
#include <cuda_runtime.h>
#include <cuda_fp16.h>
#include <cstdint>

#define N_NODES 50000
#define N_EDGES 800000
#define FEAT    128
#define NUM_RELS 8
#define NSLOT   (NUM_RELS + 1)
#define M_TILES ((N_NODES + 127) / 128)   // 391
#define PCTA    16                        // persistent CTAs per relation

#define SCAN_BLK 512
#define NB_SCAN  ((N_NODES + SCAN_BLK - 1) / SCAN_BLK)   // 98

// ---------------- scratch (__device__ globals; allocation-free rule) -------
__device__ __half d_msg[(size_t)NUM_RELS * N_NODES * FEAT];  // 102.4 MB fp16 messages (+bias)
__device__ __half d_self[(size_t)N_NODES * FEAT];            // 12.8 MB fp16 self transform (+bias)
__device__ __half d_hf[(size_t)N_NODES * FEAT];              // 12.8 MB fp16 copy of h
__device__ __half d_wt[(size_t)NSLOT * FEAT * FEAT];         // W^T fp16 [r][out][in]
__device__ int d_cnt[N_NODES];
__device__ int d_off[N_NODES];
__device__ int d_cur[N_NODES];
__device__ int d_bsum[NB_SCAN];
__device__ int d_rows[N_EDGES];                              // rel*N_NODES+src, binned by dst

// ---------------- cp.async helpers ----------------------------------------
#define CP_ASYNC16(saddr, gptr) \
    asm volatile("cp.async.cg.shared.global [%0], [%1], 16;" \
                 :: "r"(saddr), "l"(gptr) : "memory")
#define CP_COMMIT() asm volatile("cp.async.commit_group;" ::: "memory")
#define CP_WAIT0()  asm volatile("cp.async.wait_group 0;" ::: "memory")

__device__ __forceinline__ uint32_t smem_to_u32(const void* p) {
    uint32_t a;
    asm("{ .reg .u64 t; cvta.to.shared.u64 t, %1; cvt.u32.u64 %0, t; }"
        : "=r"(a) : "l"(p));
    return a;
}

// ---------------------------------------------------------------------------
// Prepass (fused): h fp32->fp16 copy  +  W transpose fp32->fp16
// ---------------------------------------------------------------------------
#define H_CHUNKS (N_NODES * FEAT / 4)     // 1.6M float4 chunks
__global__ void prep_kernel(const float* __restrict__ h, const float* __restrict__ w) {
    int idx = blockIdx.x * blockDim.x + threadIdx.x;
    if (idx < H_CHUNKS) {
        float4 v = __ldg((const float4*)h + idx);
        __half2 a = __floats2half2_rn(v.x, v.y);
        __half2 b = __floats2half2_rn(v.z, v.w);
        *((uint2*)d_hf + idx) = make_uint2(*(uint32_t*)&a, *(uint32_t*)&b);
    }
    if (idx < NSLOT * FEAT * FEAT) {
        int r   = idx / (FEAT * FEAT);
        int rem = idx - r * (FEAT * FEAT);
        int n   = rem >> 7;          // out dim
        int k   = rem & 127;         // in dim
        d_wt[idx] = __float2half_rn(
            __ldg(w + (size_t)r * FEAT * FEAT + (size_t)k * FEAT + n));
    }
}

// ---------------------------------------------------------------------------
// Phase 1: hwb[r] = h @ W[r] + b[r]; persistent CTAs, double-buffered fp16 A,
// single-pass fp16 MMA, smem-staged COALESCED epilogue
// ---------------------------------------------------------------------------
#define LDK 136                           // padded row stride in fp16 elems
#define TILE_BYTES (128 * LDK * 2)        // 34816
#define SM_A0 0
#define SM_A1 TILE_BYTES
#define SM_B  (2 * TILE_BYTES)
#define SM_ST (3 * TILE_BYTES)            // epilogue stage buffer
#define SMEM_BYTES (4 * TILE_BYTES)       // 139264

__device__ __forceinline__ void mma16816(float* c, const uint32_t* a, const uint32_t* b) {
    asm volatile(
        "mma.sync.aligned.m16n8k16.row.col.f32.f16.f16.f32 "
        "{%0,%1,%2,%3}, {%4,%5,%6,%7}, {%8,%9}, {%0,%1,%2,%3};"
        : "+f"(c[0]), "+f"(c[1]), "+f"(c[2]), "+f"(c[3])
        : "r"(a[0]), "r"(a[1]), "r"(a[2]), "r"(a[3]), "r"(b[0]), "r"(b[1]));
}

// prefetch one 128x128 fp16 A tile: 128 rows x 16 chunks(16B) = 2048 cp.async
__device__ __forceinline__ void prefetch_tile(int m0, uint32_t abuf_u32, int tid) {
#pragma unroll
    for (int it = 0; it < 8; it++) {
        int c   = it * 256 + tid;
        int row = c >> 4;
        int ch  = c & 15;                 // 16B chunk within row
        int m   = m0 + row;
        if (m > N_NODES - 1) m = N_NODES - 1;   // clamp; stores masked later
        CP_ASYNC16(abuf_u32 + (uint32_t)(row * (LDK * 2) + ch * 16),
                   d_hf + (size_t)m * FEAT + ch * 8);
    }
    CP_COMMIT();
}

__global__ void __launch_bounds__(256, 1)
gemm_mma_kernel(const float* __restrict__ bias) {
    extern __shared__ char smem[];
    __half* As[2] = { (__half*)(smem + SM_A0), (__half*)(smem + SM_A1) };
    __half* Bs    = (__half*)(smem + SM_B);
    __half* St    = (__half*)(smem + SM_ST);
    const uint32_t a_u32[2] = { smem_to_u32(As[0]), smem_to_u32(As[1]) };

    const int r    = blockIdx.x;
    const int y0   = blockIdx.y;
    const int tid  = threadIdx.x;
    const int wid  = tid >> 5;
    const int lane = tid & 31;
    const int g    = lane >> 2;          // group id 0..7
    const int t    = lane & 3;           // thread-in-group 0..3

    // warp tiling: 2 (m) x 4 (n); warp tile 64x32
    const int wm = (wid >> 2) * 64;
    const int wn = (wid & 3) * 32;

    // ---- prefetch first A tile into buffer 0 ----
    prefetch_tile(y0 * 128, a_u32[0], tid);

    // ---- B: W^T fp16 rows [n][k] — loaded ONCE per CTA ----
    const __half* bw = d_wt + (size_t)r * FEAT * FEAT;
#pragma unroll
    for (int it = 0; it < 8; it++) {
        int c    = it * 256 + tid;
        int row  = c >> 4;
        int col8 = (c & 15) << 3;
        *(uint4*)(Bs + row * LDK + col8) = *(const uint4*)(bw + (size_t)row * FEAT + col8);
    }

    // unified fp16 output target: message slot r, or the self slot
    __half* outr = (r < NUM_RELS) ? (d_msg + (size_t)r * N_NODES * FEAT) : d_self;

    // ---- persistent loop over m-tiles ----
    int cur = 0;
    for (int tile = y0; tile < M_TILES; tile += PCTA) {
        const int m0 = tile * 128;

        CP_WAIT0();
        __syncthreads();   // As[cur] ready; B visible (1st iter); As[cur^1] and
                           // St free of readers (prev tile's copy-out done)

        // prefetch next tile into the other buffer (overlaps mainloop+epilogue)
        const int nxt = tile + PCTA;
        if (nxt < M_TILES) prefetch_tile(nxt * 128, a_u32[cur ^ 1], tid);

        const __half* A = As[cur];

        // ---- mainloop: single fp16 pass ----
        float acc[4][4][4];
#pragma unroll
        for (int i = 0; i < 4; i++)
#pragma unroll
            for (int j = 0; j < 4; j++)
#pragma unroll
                for (int q = 0; q < 4; q++) acc[i][j][q] = 0.0f;

#pragma unroll
        for (int ks = 0; ks < 8; ks++) {
            const int kc = ks * 16 + 2 * t;

            uint32_t af[4][4];
#pragma unroll
            for (int mf = 0; mf < 4; mf++) {
                int r0 = (wm + mf * 16 + g) * LDK;
                int r1 = r0 + 8 * LDK;
                af[mf][0] = *(const uint32_t*)(A + r0 + kc);
                af[mf][1] = *(const uint32_t*)(A + r1 + kc);
                af[mf][2] = *(const uint32_t*)(A + r0 + kc + 8);
                af[mf][3] = *(const uint32_t*)(A + r1 + kc + 8);
            }
            uint32_t bf[4][2];
#pragma unroll
            for (int nf = 0; nf < 4; nf++) {
                int nr = (wn + nf * 8 + g) * LDK;
                bf[nf][0] = *(const uint32_t*)(Bs + nr + kc);
                bf[nf][1] = *(const uint32_t*)(Bs + nr + kc + 8);
            }
#pragma unroll
            for (int mf = 0; mf < 4; mf++)
#pragma unroll
                for (int nf = 0; nf < 4; nf++)
                    mma16816(acc[mf][nf], af[mf], bf[nf]);
        }

        // ---- epilogue stage 1: + bias, fp16 -> smem stage (conflict-free) --
#pragma unroll
        for (int nf = 0; nf < 4; nf++) {
            const int n0 = wn + nf * 8 + 2 * t;
            const float2 bv = __ldg((const float2*)(bias + (size_t)r * FEAT + n0));
#pragma unroll
            for (int mf = 0; mf < 4; mf++) {
                const int r0 = wm + mf * 16 + g;
                const int r1 = r0 + 8;
                *(__half2*)(St + r0 * LDK + n0) =
                    __floats2half2_rn(acc[mf][nf][0] + bv.x, acc[mf][nf][1] + bv.y);
                *(__half2*)(St + r1 * LDK + n0) =
                    __floats2half2_rn(acc[mf][nf][2] + bv.x, acc[mf][nf][3] + bv.y);
            }
        }
        __syncthreads();   // stage complete

        // ---- epilogue stage 2: coalesced uint4 copy-out ----
#pragma unroll
        for (int it = 0; it < 8; it++) {
            int c    = it * 256 + tid;
            int row  = c >> 4;
            int col8 = (c & 15) << 3;
            int m    = m0 + row;
            if (m < N_NODES)
                *(uint4*)(outr + (size_t)m * FEAT + col8) =
                    *(const uint4*)(St + row * LDK + col8);
        }
        cur ^= 1;
    }
}

// ---------------------------------------------------------------------------
// CSR build (side stream): zero -> count -> scanA -> scanB -> scatter
// ---------------------------------------------------------------------------
__global__ void zero_cnt_kernel() {
    int g = blockIdx.x * blockDim.x + threadIdx.x;
    if (g < N_NODES) d_cnt[g] = 0;
}

__global__ void count_kernel(const int* __restrict__ dst) {
    int e = blockIdx.x * blockDim.x + threadIdx.x;
    if (e < N_EDGES) atomicAdd(&d_cnt[__ldg(dst + e)], 1);
}

__global__ void __launch_bounds__(SCAN_BLK)
scanA_kernel() {
    __shared__ int s[SCAN_BLK];
    const int t = threadIdx.x;
    const int g = blockIdx.x * SCAN_BLK + t;
    int v = (g < N_NODES) ? d_cnt[g] : 0;
    s[t] = v;
    __syncthreads();
#pragma unroll
    for (int ofs = 1; ofs < SCAN_BLK; ofs <<= 1) {
        int add = (t >= ofs) ? s[t - ofs] : 0;
        __syncthreads();
        s[t] += add;
        __syncthreads();
    }
    if (g < N_NODES) d_off[g] = s[t] - v;           // local exclusive
    if (t == SCAN_BLK - 1) d_bsum[blockIdx.x] = s[t];
}

__global__ void __launch_bounds__(SCAN_BLK)
scanB_kernel() {
    __shared__ int bs[NB_SCAN];
    const int t = threadIdx.x;
    if (t < NB_SCAN) bs[t] = d_bsum[t];
    __syncthreads();
    int p = 0;
    for (int i = 0; i < blockIdx.x; i++) p += bs[i];
    const int g = blockIdx.x * SCAN_BLK + t;
    if (g < N_NODES) {
        int o = d_off[g] + p;
        d_off[g] = o;
        d_cur[g] = o;
    }
}

__global__ void scatter_kernel(const int* __restrict__ src,
                               const int* __restrict__ dst,
                               const int* __restrict__ rel) {
    int e = blockIdx.x * blockDim.x + threadIdx.x;
    if (e >= N_EDGES) return;
    int d = __ldg(dst + e);
    int pos = atomicAdd(&d_cur[d], 1);
    d_rows[pos] = __ldg(rel + e) * N_NODES + __ldg(src + e);
}

// ---------------------------------------------------------------------------
// Aggregation + finalize: warp per dst node, fp16 max-reduce, fused ReLU
// ---------------------------------------------------------------------------
__global__ void __launch_bounds__(256)
agg_finalize_kernel(float* __restrict__ out) {
    const int gid  = blockIdx.x * blockDim.x + threadIdx.x;
    const int nid  = gid >> 5;
    const int lane = gid & 31;
    if (nid >= N_NODES) return;

    const int deg = d_cnt[nid];
    const int off = d_off[nid];

    __half2 acc0 = __float2half2_rn(-65504.f);
    __half2 acc1 = acc0;

    int i = 0;
    for (; i + 2 <= deg; i += 2) {
        const int r0 = __ldg(&d_rows[off + i]);
        const int r1 = __ldg(&d_rows[off + i + 1]);
        const uint2 v0 = __ldg((const uint2*)(d_msg + (size_t)r0 * FEAT) + lane);
        const uint2 v1 = __ldg((const uint2*)(d_msg + (size_t)r1 * FEAT) + lane);
        acc0 = __hmax2(acc0, __hmax2(*(const __half2*)&v0.x, *(const __half2*)&v1.x));
        acc1 = __hmax2(acc1, __hmax2(*(const __half2*)&v0.y, *(const __half2*)&v1.y));
    }
    if (i < deg) {
        const int r0 = __ldg(&d_rows[off + i]);
        const uint2 v0 = __ldg((const uint2*)(d_msg + (size_t)r0 * FEAT) + lane);
        acc0 = __hmax2(acc0, *(const __half2*)&v0.x);
        acc1 = __hmax2(acc1, *(const __half2*)&v0.y);
    }

    float2 f0 = __half22float2(acc0);
    float2 f1 = __half22float2(acc1);
    if (deg == 0) { f0 = make_float2(0.f, 0.f); f1 = f0; }

    const uint2 sv = __ldg((const uint2*)(d_self + (size_t)nid * FEAT) + lane);
    const float2 s0 = __half22float2(*(const __half2*)&sv.x);
    const float2 s1 = __half22float2(*(const __half2*)&sv.y);

    float4 res;
    res.x = fmaxf(s0.x + f0.x, 0.0f);
    res.y = fmaxf(s0.y + f0.y, 0.0f);
    res.z = fmaxf(s1.x + f1.x, 0.0f);
    res.w = fmaxf(s1.y + f1.y, 0.0f);
    *(float4*)(out + (size_t)nid * FEAT + lane * 4) = res;
}

// ---------------------------------------------------------------------------
extern "C" void kernel_launch(void* const* d_in, const int* in_sizes, int n_in,
                              void* d_out, int out_size) {
    const float* h    = (const float*)d_in[0];
    const float* w    = (const float*)d_in[1];
    const float* bias = (const float*)d_in[2];
    const int*   src  = (const int*)d_in[3];
    const int*   dst  = (const int*)d_in[4];
    const int*   rel  = (const int*)d_in[5];
    float*       out  = (float*)d_out;

    // One-time resource creation (first call happens outside graph capture).
    static cudaStream_t s_side = nullptr;
    static cudaEvent_t  ev_fork = nullptr, ev_join = nullptr;
    if (!s_side) {
        cudaStreamCreateWithFlags(&s_side, cudaStreamNonBlocking);
        cudaEventCreateWithFlags(&ev_fork, cudaEventDisableTiming);
        cudaEventCreateWithFlags(&ev_join, cudaEventDisableTiming);
        cudaFuncSetAttribute(gemm_mma_kernel,
                             cudaFuncAttributeMaxDynamicSharedMemorySize, SMEM_BYTES);
    }

    // Fork: CSR build on side stream, GEMM chain on main stream.
    // Submission order keeps gemm 4th so ncu profiles it.
    cudaEventRecord(ev_fork, 0);
    cudaStreamWaitEvent(s_side, ev_fork, 0);

    zero_cnt_kernel<<<(N_NODES + 255) / 256, 256, 0, s_side>>>();       // 1
    count_kernel<<<(N_EDGES + 255) / 256, 256, 0, s_side>>>(dst);       // 2

    prep_kernel<<<(H_CHUNKS + 255) / 256, 256>>>(h, w);                 // 3 (main)
    gemm_mma_kernel<<<dim3(NSLOT, PCTA), 256, SMEM_BYTES>>>(bias);      // 4 (main)

    scanA_kernel<<<NB_SCAN, SCAN_BLK, 0, s_side>>>();                   // 5
    scanB_kernel<<<NB_SCAN, SCAN_BLK, 0, s_side>>>();                   // 6
    scatter_kernel<<<(N_EDGES + 255) / 256, 256, 0, s_side>>>(src, dst, rel); // 7

    // Join, then aggregate+finalize (depends on both branches).
    cudaEventRecord(ev_join, s_side);
    cudaStreamWaitEvent(0, ev_join, 0);

    const long long agg_threads = (long long)N_NODES * 32;
    agg_finalize_kernel<<<(int)((agg_threads + 255) / 256), 256>>>(out);
}